// round 1
// baseline (speedup 1.0000x reference)
#include <cuda_runtime.h>

#define GSZ   256
#define BB    64
#define VV    2048
#define TILE  32
#define CUTF  10.0f      // window margin: sigmoid(-20) ~ 2e-9, truncation err ~4e-6 abs

// ---------------- scratch (device globals; no allocation allowed) ----------------
__device__ float g_dens[BB * GSZ * GSZ];   // raw density (pre-blur)
__device__ float g_tmp [BB * GSZ * GSZ];   // after horizontal blur
__device__ float g_part[BB * GSZ];         // per-(b,row) loss partials
__device__ int   g_is_u8;                  // 1 if mask is uint8, 0 if int32

// ---------------- mask dtype detection ----------------
// If the bool mask were stored as int32 (LE, values 0/1), every nonzero byte
// sits at offset i%4==0. A genuine uint8 0/1 mask (~1024 ones over 2048 bytes)
// will certainly have a nonzero byte at i%4!=0. Reading 2048 bytes is safe in
// both interpretations.
__global__ void detect_mask_kernel(const unsigned char* __restrict__ m) {
    __shared__ int flag;
    if (threadIdx.x == 0) flag = 0;
    __syncthreads();
    for (int i = threadIdx.x; i < VV; i += blockDim.x)
        if ((i & 3) && m[i]) flag = 1;
    __syncthreads();
    if (threadIdx.x == 0) g_is_u8 = flag;
}

// ---------------- density: sparse windowed gather ----------------
// Block = (tile_x, tile_y, b). 256 threads.
// Phase 1: each warp w ballot-compacts its 256 cells [256w, 256w+256) into
//          seg[w][] (deterministic order). Capacity 256 is exact-max.
// Phase 2: chunks of 8 cells: 256 threads compute x_in[8][32], y_in[8][32]
//          (2 sigmoids/thread), then each thread accumulates 4 pixels.
__global__ void density_kernel(const float* __restrict__ pos,
                               const float* __restrict__ sizes,
                               const unsigned char* __restrict__ mraw)
{
    const int tx = blockIdx.x, ty = blockIdx.y, b = blockIdx.z;
    const int t = threadIdx.x;
    const int w = t >> 5, lane = t & 31;

    __shared__ int   seg[8][256];
    __shared__ int   segcnt[8];
    __shared__ float xin[8][33];   // +1 pad (not strictly needed; harmless)
    __shared__ float yin[8][33];

    const float* posb = pos + (size_t)b * VV * 2;
    const int is_u8 = g_is_u8;
    const int* mi32 = (const int*)mraw;

    const float x0 = (float)(tx * TILE), x1 = (float)(tx * TILE + TILE - 1);
    const float y0 = (float)(ty * TILE), y1 = (float)(ty * TILE + TILE - 1);

    // ---- phase 1: binning ----
    int cnt = 0;
    #pragma unroll
    for (int r = 0; r < 8; r++) {
        int v = w * 256 + r * 32 + lane;
        bool inc = false;
        bool mv = is_u8 ? (mraw[v] != 0) : (mi32[v] != 0);
        if (mv) {
            float gpx = (posb[2 * v + 0] + 1.f) * 0.5f * (GSZ - 1);
            float gpy = (posb[2 * v + 1] + 1.f) * 0.5f * (GSZ - 1);
            float rx  = sizes[2 * v + 0] * (GSZ * 0.25f) + CUTF;  // gs/2 + CUT
            float ry  = sizes[2 * v + 1] * (GSZ * 0.25f) + CUTF;
            inc = (gpx + rx >= x0) && (gpx - rx <= x1) &&
                  (gpy + ry >= y0) && (gpy - ry <= y1);
        }
        unsigned bm = __ballot_sync(0xffffffffu, inc);
        if (inc) {
            int p = cnt + __popc(bm & ((1u << lane) - 1u));
            seg[w][p] = v;
        }
        cnt += __popc(bm);
    }
    if (lane == 0) segcnt[w] = cnt;
    __syncthreads();

    // ---- phase 2: accumulate ----
    float acc0 = 0.f, acc1 = 0.f, acc2 = 0.f, acc3 = 0.f;
    const int px = lane;      // x within tile
    const int py = w;         // y rows: py, py+8, py+16, py+24

    for (int s = 0; s < 8; s++) {
        const int n = segcnt[s];
        for (int base = 0; base < n; base += 8) {
            // compute fields for up to 8 cells: thread (c=w, j=lane)
            if (base + w < n) {
                int v = seg[s][base + w];
                float gpx = (posb[2 * v + 0] + 1.f) * 0.5f * (GSZ - 1);
                float gpy = (posb[2 * v + 1] + 1.f) * 0.5f * (GSZ - 1);
                float hx  = sizes[2 * v + 0] * (GSZ * 0.25f);
                float hy  = sizes[2 * v + 1] * (GSZ * 0.25f);
                float cx  = (float)(tx * TILE + lane);
                float cy  = (float)(ty * TILE + lane);
                float ax  = (hx - fabsf(cx - gpx)) * 2.f;
                float ay  = (hy - fabsf(cy - gpy)) * 2.f;
                xin[w][lane] = 1.f / (1.f + __expf(-ax));
                yin[w][lane] = 1.f / (1.f + __expf(-ay));
            }
            __syncthreads();
            int ce = n - base; if (ce > 8) ce = 8;
            #pragma unroll 8
            for (int c = 0; c < ce; c++) {
                float xv = xin[c][px];
                acc0 += xv * yin[c][py];
                acc1 += xv * yin[c][py + 8];
                acc2 += xv * yin[c][py + 16];
                acc3 += xv * yin[c][py + 24];
            }
            __syncthreads();
        }
    }

    const size_t ob = (size_t)b * GSZ * GSZ;
    const int gx = tx * TILE + px;
    g_dens[ob + (size_t)(ty * TILE + py     ) * GSZ + gx] = acc0;
    g_dens[ob + (size_t)(ty * TILE + py +  8) * GSZ + gx] = acc1;
    g_dens[ob + (size_t)(ty * TILE + py + 16) * GSZ + gx] = acc2;
    g_dens[ob + (size_t)(ty * TILE + py + 24) * GSZ + gx] = acc3;
}

// ---------------- separable 13-tap Gaussian blur (sigma=2, reflect pad) ----------------
__device__ __forceinline__ void gauss_w(float* wgt) {
    float s = 0.f;
    #pragma unroll
    for (int i = 0; i < 13; i++) {
        float d = (float)(i - 6);
        wgt[i] = __expf(-d * d * 0.125f);   // exp(-d^2 / (2*sigma^2)), sigma=2
        s += wgt[i];
    }
    float inv = 1.f / s;
    #pragma unroll
    for (int i = 0; i < 13; i++) wgt[i] *= inv;
}

__device__ __forceinline__ int reflect_idx(int j) {
    j = (j < 0) ? -j : j;
    return (j > GSZ - 1) ? (2 * (GSZ - 1) - j) : j;
}

__global__ void blur_h_kernel() {
    const int y = blockIdx.x, b = blockIdx.y, x = threadIdx.x;
    __shared__ float row[GSZ];
    const size_t base = ((size_t)b * GSZ + y) * GSZ;
    row[x] = g_dens[base + x];
    float wgt[13]; gauss_w(wgt);
    __syncthreads();
    float a = 0.f;
    #pragma unroll
    for (int i = 0; i < 13; i++)
        a += wgt[i] * row[reflect_idx(x + i - 6)];
    g_tmp[base + x] = a;
}

__global__ void blur_v_kernel(float* __restrict__ out) {
    const int y = blockIdx.x, b = blockIdx.y, x = threadIdx.x;
    float wgt[13]; gauss_w(wgt);
    const size_t bb = (size_t)b * GSZ * GSZ;
    float a = 0.f;
    #pragma unroll
    for (int i = 0; i < 13; i++)
        a += wgt[i] * g_tmp[bb + (size_t)reflect_idx(y + i - 6) * GSZ + x];
    out[bb + (size_t)y * GSZ + x] = a;

    // fused overflow-loss partial (deterministic tree reduce)
    float v = a - 1.0f; v = (v > 0.f) ? v : 0.f;
    __shared__ float red[GSZ];
    red[x] = v * v;
    __syncthreads();
    #pragma unroll
    for (int st = 128; st > 0; st >>= 1) {
        if (x < st) red[x] += red[x + st];
        __syncthreads();
    }
    if (x == 0) g_part[b * GSZ + y] = red[0];
}

__global__ void loss_final_kernel(float* __restrict__ out, int out_size) {
    const int t = threadIdx.x;   // 256 threads
    double s = 0.0;
    for (int i = t; i < BB * GSZ; i += 256) s += (double)g_part[i];
    __shared__ double red[256];
    red[t] = s;
    __syncthreads();
    #pragma unroll
    for (int st = 128; st > 0; st >>= 1) {
        if (t < st) red[t] += red[t + st];
        __syncthreads();
    }
    const int nden = BB * GSZ * GSZ;
    if (t == 0 && out_size > nden)
        out[nden] = (float)(red[0] / (double)nden);
}

// ---------------- launch ----------------
extern "C" void kernel_launch(void* const* d_in, const int* in_sizes, int n_in,
                              void* d_out, int out_size) {
    (void)in_sizes; (void)n_in;
    const float*         pos   = (const float*)d_in[0];
    const float*         sizes = (const float*)d_in[1];
    const unsigned char* mask  = (const unsigned char*)d_in[2];
    float* out = (float*)d_out;

    detect_mask_kernel<<<1, 256>>>(mask);
    density_kernel<<<dim3(GSZ / TILE, GSZ / TILE, BB), 256>>>(pos, sizes, mask);
    blur_h_kernel<<<dim3(GSZ, BB), GSZ>>>();
    blur_v_kernel<<<dim3(GSZ, BB), GSZ>>>(out);
    loss_final_kernel<<<1, 256>>>(out, out_size);
}

// round 2
// speedup vs baseline: 1.0008x; 1.0008x over previous
#include <cuda_runtime.h>

#define GSZ   256
#define BB    64
#define VV    2048
#define TILE  32
#define CUTF  10.0f      // window margin: sigmoid(-20) ~ 2e-9, truncation err ~4e-6 abs

// ---------------- scratch (device globals; no allocation allowed) ----------------
__device__ float g_dens[BB * GSZ * GSZ];   // raw density (pre-blur)
__device__ float g_tmp [BB * GSZ * GSZ];   // after horizontal blur
__device__ float g_part[BB * GSZ];         // per-(b,row) loss partials
__device__ int   g_is_u8;                  // 1 if mask is uint8, 0 if int32

// ---------------- mask dtype detection ----------------
// If the bool mask were stored as int32 (LE, values 0/1), every nonzero byte
// sits at offset i%4==0. A genuine uint8 0/1 mask (~1024 ones over 2048 bytes)
// will certainly have a nonzero byte at i%4!=0. Reading 2048 bytes is safe in
// both interpretations.
__global__ void detect_mask_kernel(const unsigned char* __restrict__ m) {
    __shared__ int flag;
    if (threadIdx.x == 0) flag = 0;
    __syncthreads();
    for (int i = threadIdx.x; i < VV; i += blockDim.x)
        if ((i & 3) && m[i]) flag = 1;
    __syncthreads();
    if (threadIdx.x == 0) g_is_u8 = flag;
}

// ---------------- density: sparse windowed gather ----------------
// Block = (tile_x, tile_y, b). 256 threads.
// Phase 1: each warp w ballot-compacts its 256 cells [256w, 256w+256) into
//          seg[w][] (deterministic order). Capacity 256 is exact-max.
// Phase 2: chunks of 8 cells: 256 threads compute x_in[8][32], y_in[8][32]
//          (2 sigmoids/thread), then each thread accumulates 4 pixels.
__global__ void density_kernel(const float* __restrict__ pos,
                               const float* __restrict__ sizes,
                               const unsigned char* __restrict__ mraw)
{
    const int tx = blockIdx.x, ty = blockIdx.y, b = blockIdx.z;
    const int t = threadIdx.x;
    const int w = t >> 5, lane = t & 31;

    __shared__ int   seg[8][256];
    __shared__ int   segcnt[8];
    __shared__ float xin[8][33];   // +1 pad (not strictly needed; harmless)
    __shared__ float yin[8][33];

    const float* posb = pos + (size_t)b * VV * 2;
    const int is_u8 = g_is_u8;
    const int* mi32 = (const int*)mraw;

    const float x0 = (float)(tx * TILE), x1 = (float)(tx * TILE + TILE - 1);
    const float y0 = (float)(ty * TILE), y1 = (float)(ty * TILE + TILE - 1);

    // ---- phase 1: binning ----
    int cnt = 0;
    #pragma unroll
    for (int r = 0; r < 8; r++) {
        int v = w * 256 + r * 32 + lane;
        bool inc = false;
        bool mv = is_u8 ? (mraw[v] != 0) : (mi32[v] != 0);
        if (mv) {
            float gpx = (posb[2 * v + 0] + 1.f) * 0.5f * (GSZ - 1);
            float gpy = (posb[2 * v + 1] + 1.f) * 0.5f * (GSZ - 1);
            float rx  = sizes[2 * v + 0] * (GSZ * 0.25f) + CUTF;  // gs/2 + CUT
            float ry  = sizes[2 * v + 1] * (GSZ * 0.25f) + CUTF;
            inc = (gpx + rx >= x0) && (gpx - rx <= x1) &&
                  (gpy + ry >= y0) && (gpy - ry <= y1);
        }
        unsigned bm = __ballot_sync(0xffffffffu, inc);
        if (inc) {
            int p = cnt + __popc(bm & ((1u << lane) - 1u));
            seg[w][p] = v;
        }
        cnt += __popc(bm);
    }
    if (lane == 0) segcnt[w] = cnt;
    __syncthreads();

    // ---- phase 2: accumulate ----
    float acc0 = 0.f, acc1 = 0.f, acc2 = 0.f, acc3 = 0.f;
    const int px = lane;      // x within tile
    const int py = w;         // y rows: py, py+8, py+16, py+24

    for (int s = 0; s < 8; s++) {
        const int n = segcnt[s];
        for (int base = 0; base < n; base += 8) {
            // compute fields for up to 8 cells: thread (c=w, j=lane)
            if (base + w < n) {
                int v = seg[s][base + w];
                float gpx = (posb[2 * v + 0] + 1.f) * 0.5f * (GSZ - 1);
                float gpy = (posb[2 * v + 1] + 1.f) * 0.5f * (GSZ - 1);
                float hx  = sizes[2 * v + 0] * (GSZ * 0.25f);
                float hy  = sizes[2 * v + 1] * (GSZ * 0.25f);
                float cx  = (float)(tx * TILE + lane);
                float cy  = (float)(ty * TILE + lane);
                float ax  = (hx - fabsf(cx - gpx)) * 2.f;
                float ay  = (hy - fabsf(cy - gpy)) * 2.f;
                xin[w][lane] = 1.f / (1.f + __expf(-ax));
                yin[w][lane] = 1.f / (1.f + __expf(-ay));
            }
            __syncthreads();
            int ce = n - base; if (ce > 8) ce = 8;
            #pragma unroll 8
            for (int c = 0; c < ce; c++) {
                float xv = xin[c][px];
                acc0 += xv * yin[c][py];
                acc1 += xv * yin[c][py + 8];
                acc2 += xv * yin[c][py + 16];
                acc3 += xv * yin[c][py + 24];
            }
            __syncthreads();
        }
    }

    const size_t ob = (size_t)b * GSZ * GSZ;
    const int gx = tx * TILE + px;
    g_dens[ob + (size_t)(ty * TILE + py     ) * GSZ + gx] = acc0;
    g_dens[ob + (size_t)(ty * TILE + py +  8) * GSZ + gx] = acc1;
    g_dens[ob + (size_t)(ty * TILE + py + 16) * GSZ + gx] = acc2;
    g_dens[ob + (size_t)(ty * TILE + py + 24) * GSZ + gx] = acc3;
}

// ---------------- separable 13-tap Gaussian blur (sigma=2, reflect pad) ----------------
__device__ __forceinline__ void gauss_w(float* wgt) {
    float s = 0.f;
    #pragma unroll
    for (int i = 0; i < 13; i++) {
        float d = (float)(i - 6);
        wgt[i] = __expf(-d * d * 0.125f);   // exp(-d^2 / (2*sigma^2)), sigma=2
        s += wgt[i];
    }
    float inv = 1.f / s;
    #pragma unroll
    for (int i = 0; i < 13; i++) wgt[i] *= inv;
}

__device__ __forceinline__ int reflect_idx(int j) {
    j = (j < 0) ? -j : j;
    return (j > GSZ - 1) ? (2 * (GSZ - 1) - j) : j;
}

__global__ void blur_h_kernel() {
    const int y = blockIdx.x, b = blockIdx.y, x = threadIdx.x;
    __shared__ float row[GSZ];
    const size_t base = ((size_t)b * GSZ + y) * GSZ;
    row[x] = g_dens[base + x];
    float wgt[13]; gauss_w(wgt);
    __syncthreads();
    float a = 0.f;
    #pragma unroll
    for (int i = 0; i < 13; i++)
        a += wgt[i] * row[reflect_idx(x + i - 6)];
    g_tmp[base + x] = a;
}

__global__ void blur_v_kernel(float* __restrict__ out) {
    const int y = blockIdx.x, b = blockIdx.y, x = threadIdx.x;
    float wgt[13]; gauss_w(wgt);
    const size_t bb = (size_t)b * GSZ * GSZ;
    float a = 0.f;
    #pragma unroll
    for (int i = 0; i < 13; i++)
        a += wgt[i] * g_tmp[bb + (size_t)reflect_idx(y + i - 6) * GSZ + x];
    out[bb + (size_t)y * GSZ + x] = a;

    // fused overflow-loss partial (deterministic tree reduce)
    float v = a - 1.0f; v = (v > 0.f) ? v : 0.f;
    __shared__ float red[GSZ];
    red[x] = v * v;
    __syncthreads();
    #pragma unroll
    for (int st = 128; st > 0; st >>= 1) {
        if (x < st) red[x] += red[x + st];
        __syncthreads();
    }
    if (x == 0) g_part[b * GSZ + y] = red[0];
}

__global__ void loss_final_kernel(float* __restrict__ out, int out_size) {
    const int t = threadIdx.x;   // 256 threads
    double s = 0.0;
    for (int i = t; i < BB * GSZ; i += 256) s += (double)g_part[i];
    __shared__ double red[256];
    red[t] = s;
    __syncthreads();
    #pragma unroll
    for (int st = 128; st > 0; st >>= 1) {
        if (t < st) red[t] += red[t + st];
        __syncthreads();
    }
    const int nden = BB * GSZ * GSZ;
    if (t == 0 && out_size > nden)
        out[nden] = (float)(red[0] / (double)nden);
}

// ---------------- launch ----------------
extern "C" void kernel_launch(void* const* d_in, const int* in_sizes, int n_in,
                              void* d_out, int out_size) {
    (void)in_sizes; (void)n_in;
    const float*         pos   = (const float*)d_in[0];
    const float*         sizes = (const float*)d_in[1];
    const unsigned char* mask  = (const unsigned char*)d_in[2];
    float* out = (float*)d_out;

    detect_mask_kernel<<<1, 256>>>(mask);
    density_kernel<<<dim3(GSZ / TILE, GSZ / TILE, BB), 256>>>(pos, sizes, mask);
    blur_h_kernel<<<dim3(GSZ, BB), GSZ>>>();
    blur_v_kernel<<<dim3(GSZ, BB), GSZ>>>(out);
    loss_final_kernel<<<1, 256>>>(out, out_size);
}

// round 3
// speedup vs baseline: 1.0011x; 1.0003x over previous
#include <cuda_runtime.h>

#define GSZ   256
#define BB    64
#define VV    2048
#define TILE  32
#define CUTF  10.0f      // window margin: sigmoid(-20) ~ 2e-9, truncation err ~4e-6 abs

// ---------------- scratch (device globals; no allocation allowed) ----------------
__device__ float g_dens[BB * GSZ * GSZ];   // raw density (pre-blur)
__device__ float g_tmp [BB * GSZ * GSZ];   // after horizontal blur
__device__ float g_part[BB * GSZ];         // per-(b,row) loss partials
__device__ int   g_is_u8;                  // 1 if mask is uint8, 0 if int32

// ---------------- mask dtype detection ----------------
// If the bool mask were stored as int32 (LE, values 0/1), every nonzero byte
// sits at offset i%4==0. A genuine uint8 0/1 mask (~1024 ones over 2048 bytes)
// will certainly have a nonzero byte at i%4!=0. Reading 2048 bytes is safe in
// both interpretations.
__global__ void detect_mask_kernel(const unsigned char* __restrict__ m) {
    __shared__ int flag;
    if (threadIdx.x == 0) flag = 0;
    __syncthreads();
    for (int i = threadIdx.x; i < VV; i += blockDim.x)
        if ((i & 3) && m[i]) flag = 1;
    __syncthreads();
    if (threadIdx.x == 0) g_is_u8 = flag;
}

// ---------------- density: sparse windowed gather ----------------
// Block = (tile_x, tile_y, b). 256 threads.
// Phase 1: each warp w ballot-compacts its 256 cells [256w, 256w+256) into
//          seg[w][] (deterministic order). Capacity 256 is exact-max.
// Phase 2: chunks of 8 cells: 256 threads compute x_in[8][32], y_in[8][32]
//          (2 sigmoids/thread), then each thread accumulates 4 pixels.
__global__ void density_kernel(const float* __restrict__ pos,
                               const float* __restrict__ sizes,
                               const unsigned char* __restrict__ mraw)
{
    const int tx = blockIdx.x, ty = blockIdx.y, b = blockIdx.z;
    const int t = threadIdx.x;
    const int w = t >> 5, lane = t & 31;

    __shared__ int   seg[8][256];
    __shared__ int   segcnt[8];
    __shared__ float xin[8][33];   // +1 pad (not strictly needed; harmless)
    __shared__ float yin[8][33];

    const float* posb = pos + (size_t)b * VV * 2;
    const int is_u8 = g_is_u8;
    const int* mi32 = (const int*)mraw;

    const float x0 = (float)(tx * TILE), x1 = (float)(tx * TILE + TILE - 1);
    const float y0 = (float)(ty * TILE), y1 = (float)(ty * TILE + TILE - 1);

    // ---- phase 1: binning ----
    int cnt = 0;
    #pragma unroll
    for (int r = 0; r < 8; r++) {
        int v = w * 256 + r * 32 + lane;
        bool inc = false;
        bool mv = is_u8 ? (mraw[v] != 0) : (mi32[v] != 0);
        if (mv) {
            float gpx = (posb[2 * v + 0] + 1.f) * 0.5f * (GSZ - 1);
            float gpy = (posb[2 * v + 1] + 1.f) * 0.5f * (GSZ - 1);
            float rx  = sizes[2 * v + 0] * (GSZ * 0.25f) + CUTF;  // gs/2 + CUT
            float ry  = sizes[2 * v + 1] * (GSZ * 0.25f) + CUTF;
            inc = (gpx + rx >= x0) && (gpx - rx <= x1) &&
                  (gpy + ry >= y0) && (gpy - ry <= y1);
        }
        unsigned bm = __ballot_sync(0xffffffffu, inc);
        if (inc) {
            int p = cnt + __popc(bm & ((1u << lane) - 1u));
            seg[w][p] = v;
        }
        cnt += __popc(bm);
    }
    if (lane == 0) segcnt[w] = cnt;
    __syncthreads();

    // ---- phase 2: accumulate ----
    float acc0 = 0.f, acc1 = 0.f, acc2 = 0.f, acc3 = 0.f;
    const int px = lane;      // x within tile
    const int py = w;         // y rows: py, py+8, py+16, py+24

    for (int s = 0; s < 8; s++) {
        const int n = segcnt[s];
        for (int base = 0; base < n; base += 8) {
            // compute fields for up to 8 cells: thread (c=w, j=lane)
            if (base + w < n) {
                int v = seg[s][base + w];
                float gpx = (posb[2 * v + 0] + 1.f) * 0.5f * (GSZ - 1);
                float gpy = (posb[2 * v + 1] + 1.f) * 0.5f * (GSZ - 1);
                float hx  = sizes[2 * v + 0] * (GSZ * 0.25f);
                float hy  = sizes[2 * v + 1] * (GSZ * 0.25f);
                float cx  = (float)(tx * TILE + lane);
                float cy  = (float)(ty * TILE + lane);
                float ax  = (hx - fabsf(cx - gpx)) * 2.f;
                float ay  = (hy - fabsf(cy - gpy)) * 2.f;
                xin[w][lane] = 1.f / (1.f + __expf(-ax));
                yin[w][lane] = 1.f / (1.f + __expf(-ay));
            }
            __syncthreads();
            int ce = n - base; if (ce > 8) ce = 8;
            #pragma unroll 8
            for (int c = 0; c < ce; c++) {
                float xv = xin[c][px];
                acc0 += xv * yin[c][py];
                acc1 += xv * yin[c][py + 8];
                acc2 += xv * yin[c][py + 16];
                acc3 += xv * yin[c][py + 24];
            }
            __syncthreads();
        }
    }

    const size_t ob = (size_t)b * GSZ * GSZ;
    const int gx = tx * TILE + px;
    g_dens[ob + (size_t)(ty * TILE + py     ) * GSZ + gx] = acc0;
    g_dens[ob + (size_t)(ty * TILE + py +  8) * GSZ + gx] = acc1;
    g_dens[ob + (size_t)(ty * TILE + py + 16) * GSZ + gx] = acc2;
    g_dens[ob + (size_t)(ty * TILE + py + 24) * GSZ + gx] = acc3;
}

// ---------------- separable 13-tap Gaussian blur (sigma=2, reflect pad) ----------------
__device__ __forceinline__ void gauss_w(float* wgt) {
    float s = 0.f;
    #pragma unroll
    for (int i = 0; i < 13; i++) {
        float d = (float)(i - 6);
        wgt[i] = __expf(-d * d * 0.125f);   // exp(-d^2 / (2*sigma^2)), sigma=2
        s += wgt[i];
    }
    float inv = 1.f / s;
    #pragma unroll
    for (int i = 0; i < 13; i++) wgt[i] *= inv;
}

__device__ __forceinline__ int reflect_idx(int j) {
    j = (j < 0) ? -j : j;
    return (j > GSZ - 1) ? (2 * (GSZ - 1) - j) : j;
}

__global__ void blur_h_kernel() {
    const int y = blockIdx.x, b = blockIdx.y, x = threadIdx.x;
    __shared__ float row[GSZ];
    const size_t base = ((size_t)b * GSZ + y) * GSZ;
    row[x] = g_dens[base + x];
    float wgt[13]; gauss_w(wgt);
    __syncthreads();
    float a = 0.f;
    #pragma unroll
    for (int i = 0; i < 13; i++)
        a += wgt[i] * row[reflect_idx(x + i - 6)];
    g_tmp[base + x] = a;
}

__global__ void blur_v_kernel(float* __restrict__ out) {
    const int y = blockIdx.x, b = blockIdx.y, x = threadIdx.x;
    float wgt[13]; gauss_w(wgt);
    const size_t bb = (size_t)b * GSZ * GSZ;
    float a = 0.f;
    #pragma unroll
    for (int i = 0; i < 13; i++)
        a += wgt[i] * g_tmp[bb + (size_t)reflect_idx(y + i - 6) * GSZ + x];
    out[bb + (size_t)y * GSZ + x] = a;

    // fused overflow-loss partial (deterministic tree reduce)
    float v = a - 1.0f; v = (v > 0.f) ? v : 0.f;
    __shared__ float red[GSZ];
    red[x] = v * v;
    __syncthreads();
    #pragma unroll
    for (int st = 128; st > 0; st >>= 1) {
        if (x < st) red[x] += red[x + st];
        __syncthreads();
    }
    if (x == 0) g_part[b * GSZ + y] = red[0];
}

__global__ void loss_final_kernel(float* __restrict__ out, int out_size) {
    const int t = threadIdx.x;   // 256 threads
    double s = 0.0;
    for (int i = t; i < BB * GSZ; i += 256) s += (double)g_part[i];
    __shared__ double red[256];
    red[t] = s;
    __syncthreads();
    #pragma unroll
    for (int st = 128; st > 0; st >>= 1) {
        if (t < st) red[t] += red[t + st];
        __syncthreads();
    }
    const int nden = BB * GSZ * GSZ;
    if (t == 0 && out_size > nden)
        out[nden] = (float)(red[0] / (double)nden);
}

// ---------------- launch ----------------
extern "C" void kernel_launch(void* const* d_in, const int* in_sizes, int n_in,
                              void* d_out, int out_size) {
    (void)in_sizes; (void)n_in;
    const float*         pos   = (const float*)d_in[0];
    const float*         sizes = (const float*)d_in[1];
    const unsigned char* mask  = (const unsigned char*)d_in[2];
    float* out = (float*)d_out;

    detect_mask_kernel<<<1, 256>>>(mask);
    density_kernel<<<dim3(GSZ / TILE, GSZ / TILE, BB), 256>>>(pos, sizes, mask);
    blur_h_kernel<<<dim3(GSZ, BB), GSZ>>>();
    blur_v_kernel<<<dim3(GSZ, BB), GSZ>>>(out);
    loss_final_kernel<<<1, 256>>>(out, out_size);
}